// round 17
// baseline (speedup 1.0000x reference)
#include <cuda_runtime.h>
#include <cuda_fp16.h>
#include <math.h>
#include <stdint.h>

#define EMB    128
#define HEADS  8
#define NB     8
#define SEQ    2048
#define BT     (NB*SEQ)          // 16384
#define HE     (HEADS*EMB)       // 1024
#define QKSCALE 0.08838834764831845f   // 1/sqrt(128)
#define LOG2E   1.4426950408889634f

// Scratch (fp16)
__device__ __half g_Xh [BT*EMB];          // x converted
__device__ __half g_Wqh[EMB*HE];
__device__ __half g_Wkh[EMB*HE];
__device__ __half g_Wvh[EMB*HE];
__device__ __half g_Woh[HE*EMB];
__device__ __half g_Qh [NB*HEADS*SEQ*EMB];
__device__ __half g_Kh [NB*HEADS*SEQ*EMB];
__device__ __half g_Vh [NB*HEADS*SEQ*EMB];
__device__ __half g_Ah [NB*SEQ*HEADS*EMB];

// ---------------------------------------------------------------------------
// Baseline-ISA PTX helpers (compile for sm_103 without 'a' suffix)
// ---------------------------------------------------------------------------
__device__ __forceinline__ uint32_t smem_u32(const void* p) {
    return (uint32_t)__cvta_generic_to_shared(p);
}
__device__ __forceinline__ void mma16816(float* c, const uint32_t* a, const uint32_t* b) {
    asm volatile("mma.sync.aligned.m16n8k16.row.col.f32.f16.f16.f32 "
                 "{%0,%1,%2,%3}, {%4,%5,%6,%7}, {%8,%9}, {%0,%1,%2,%3};"
                 : "+f"(c[0]), "+f"(c[1]), "+f"(c[2]), "+f"(c[3])
                 : "r"(a[0]), "r"(a[1]), "r"(a[2]), "r"(a[3]), "r"(b[0]), "r"(b[1]));
}
__device__ __forceinline__ void ldsm4(uint32_t* r, uint32_t a) {
    asm volatile("ldmatrix.sync.aligned.m8n8.x4.shared.b16 {%0,%1,%2,%3}, [%4];"
                 : "=r"(r[0]), "=r"(r[1]), "=r"(r[2]), "=r"(r[3]) : "r"(a));
}
__device__ __forceinline__ void ldsm4t(uint32_t* r, uint32_t a) {
    asm volatile("ldmatrix.sync.aligned.m8n8.x4.trans.shared.b16 {%0,%1,%2,%3}, [%4];"
                 : "=r"(r[0]), "=r"(r[1]), "=r"(r[2]), "=r"(r[3]) : "r"(a));
}
__device__ __forceinline__ void cpa16(uint32_t s, const void* g) {
    asm volatile("cp.async.ca.shared.global [%0], [%1], 16;" :: "r"(s), "l"(g));
}
__device__ __forceinline__ void cpa_commit() {
    asm volatile("cp.async.commit_group;" ::: "memory");
}
__device__ __forceinline__ void cpa_wait0() {
    asm volatile("cp.async.wait_group 0;" ::: "memory");
}
__device__ __forceinline__ uint32_t pk_h2(__half a, __half b) {
    return (uint32_t)__half_as_ushort(a) | ((uint32_t)__half_as_ushort(b) << 16);
}
// packed fp16 exp2: d = { exp2(slo) , exp2(shi) } as half2 (lo,hi)
__device__ __forceinline__ uint32_t exp2_h2(float slo, float shi) {
    uint32_t u;
    asm("{\n\t.reg .b32 t;\n\t"
        "cvt.rn.f16x2.f32 t, %1, %2;\n\t"
        "ex2.approx.f16x2 %0, t;\n\t}"
        : "=r"(u) : "f"(shi), "f"(slo));
    return u;
}

#define XROW 272

// ---------------------------------------------------------------------------
// Kernel 0: one-shot fp32 -> fp16 conversion of x, Wq, Wk, Wv, Wo.
// ---------------------------------------------------------------------------
__global__ __launch_bounds__(256) void prep_kernel(
    const float* __restrict__ x,
    const float* __restrict__ Wq,
    const float* __restrict__ Wk,
    const float* __restrict__ Wv,
    const float* __restrict__ Wo)
{
    const int z = blockIdx.y;
    const float* src;
    __half* dst;
    int n;
    if      (z == 0) { src = x;  dst = g_Xh;  n = BT * EMB; }
    else if (z == 1) { src = Wq; dst = g_Wqh; n = EMB * HE; }
    else if (z == 2) { src = Wk; dst = g_Wkh; n = EMB * HE; }
    else if (z == 3) { src = Wv; dst = g_Wvh; n = EMB * HE; }
    else             { src = Wo; dst = g_Woh; n = HE * EMB; }

    int idx = (blockIdx.x * 256 + threadIdx.x) * 8;
    if (idx < n) {
        float4 a = *(const float4*)(src + idx);
        float4 b = *(const float4*)(src + idx + 4);
        uint4 o;
        o.x = pk_h2(__float2half_rn(a.x), __float2half_rn(a.y));
        o.y = pk_h2(__float2half_rn(a.z), __float2half_rn(a.w));
        o.z = pk_h2(__float2half_rn(b.x), __float2half_rn(b.y));
        o.w = pk_h2(__float2half_rn(b.z), __float2half_rn(b.w));
        *(uint4*)(dst + idx) = o;
    }
}

// ---------------------------------------------------------------------------
// Kernel 1: QKV projection (unchanged from R16).
// ---------------------------------------------------------------------------
#define QK_X  0
#define QK_W0 17408
#define QK_W1 52224
#define QKV_SMEM 87040

__global__ __launch_bounds__(256, 2) void qkv_tc_kernel()
{
    extern __shared__ char sm[];
    const uint32_t sb = smem_u32(sm);

    const int tid  = threadIdx.x;
    const int wid  = tid >> 5;
    const int lane = tid & 31;
    const int mw   = wid & 3;
    const int nw   = wid >> 2;
    const int mc   = blockIdx.x * 64;
    const int z    = blockIdx.y;
    const __half* W = (z == 0) ? g_Wqh : ((z == 1) ? g_Wkh : g_Wvh);
    __half* dst     = (z == 0) ? g_Qh : ((z == 1) ? g_Kh : g_Vh);
    const float sc  = (z == 0) ? (QKSCALE * LOG2E) : 1.0f;

#pragma unroll
    for (int i = 0; i < 4; i++) {
        int idx = tid + i * 256;
        int r = idx >> 4, ch = idx & 15;
        cpa16(sb + QK_X + r * XROW + ch * 16, g_Xh + (size_t)(mc + r) * EMB + ch * 8);
    }
#pragma unroll
    for (int i = 0; i < 8; i++) {
        int idx = tid + i * 256;
        int r = idx >> 4, ch = idx & 15;
        cpa16(sb + QK_W0 + r * XROW + ch * 16, W + (size_t)r * HE + ch * 8);
    }
    cpa_commit();

    const int lr = (lane & 7) + ((lane >> 3) & 1) * 8;
    const int lc = (lane >> 4) * 8;
    const uint32_t aX = sb + QK_X + (mw * 16 + lr) * XROW + lc * 2;
    const int vrow = (lane & 7) + ((lane >> 3) & 1) * 8;
    const int vcol = ((lane >> 4) & 1) * 8;
    const uint32_t wfrag = vrow * XROW + (nw * 64 + vcol) * 2;

    const int r0  = mw * 16 + (lane >> 2);
    const int m   = mc + r0;
    const int bb  = m >> 11;
    const int t   = m & (SEQ - 1);

    for (int hh = 0; hh < HEADS; hh++) {
        cpa_wait0();
        __syncthreads();

        if (hh < 7) {
            uint32_t nb = sb + ((hh + 1) & 1 ? QK_W1 : QK_W0);
#pragma unroll
            for (int i = 0; i < 8; i++) {
                int idx = tid + i * 256;
                int r = idx >> 4, ch = idx & 15;
                cpa16(nb + r * XROW + ch * 16,
                      W + (size_t)r * HE + (hh + 1) * 128 + ch * 8);
            }
            cpa_commit();
        }

        const uint32_t bW = sb + ((hh & 1) ? QK_W1 : QK_W0) + wfrag;

        float Oa[8][4];
#pragma unroll
        for (int tt = 0; tt < 8; tt++)
#pragma unroll
            for (int j = 0; j < 4; j++) Oa[tt][j] = 0.f;

#pragma unroll
        for (int ks = 0; ks < 8; ks++) {
            uint32_t xh[4];
            ldsm4(xh, aX + ks * 32);
#pragma unroll
            for (int nt = 0; nt < 4; nt++) {
                uint32_t wh[4];
                ldsm4t(wh, bW + ks * 16 * XROW + nt * 32);
                mma16816(Oa[2 * nt],     xh, wh);
                mma16816(Oa[2 * nt + 1], xh, wh + 2);
            }
        }

        const size_t base = ((size_t)(bb * HEADS + hh) * SEQ + t) * EMB;
#pragma unroll
        for (int tt = 0; tt < 8; tt++) {
            int e = nw * 64 + (tt >> 1) * 16 + (tt & 1) * 8 + (lane & 3) * 2;
            *(uint32_t*)&dst[base + e] =
                pk_h2(__float2half_rn(Oa[tt][0] * sc), __float2half_rn(Oa[tt][1] * sc));
            *(uint32_t*)&dst[base + 8 * EMB + e] =
                pk_h2(__float2half_rn(Oa[tt][2] * sc), __float2half_rn(Oa[tt][3] * sc));
        }
    }
}

// ---------------------------------------------------------------------------
// Kernel 2: mma.sync fp16 attention. Restructured into four independent
// 16-key blocks per tile (S -> exp2 -> PV per block) so the scheduler
// overlaps tensor / MUFU / ldsm phases across blocks. Q fragments hoisted
// to registers per tile. Accumulation order identical to R16.
// ---------------------------------------------------------------------------
#define QROW 272
#define SM_Q  0              // 128*272 = 34816
#define SM_KV 34816          // 2 buffers x (K 17408 + V 17408)
#define ATTN_SMEM 104448

__global__ __launch_bounds__(256, 2) void attn_mma_kernel()
{
    extern __shared__ char sm[];
    const uint32_t sb = smem_u32(sm);

    const int tid  = threadIdx.x;
    const int wid  = tid >> 5;
    const int lane = tid & 31;
    const int bh   = blockIdx.y;
    const int q0   = blockIdx.x * 128;
    const int m0   = wid * 16;

    const __half* Qg = g_Qh + (size_t)bh * SEQ * EMB + (size_t)q0 * EMB;
    const __half* Kg = g_Kh + (size_t)bh * SEQ * EMB;
    const __half* Vg = g_Vh + (size_t)bh * SEQ * EMB;

#pragma unroll
    for (int i = 0; i < 8; i++) {
        int idx = tid + i * 256;
        int r = idx >> 4, ch = idx & 15;
        cpa16(sb + SM_Q + r * QROW + ch * 16, Qg + r * EMB + ch * 8);
    }
#pragma unroll
    for (int i = 0; i < 4; i++) {
        int idx = tid + i * 256;
        int r = idx >> 4, ch = idx & 15;
        cpa16(sb + SM_KV + r * QROW + ch * 16,         Kg + r * EMB + ch * 8);
        cpa16(sb + SM_KV + 17408 + r * QROW + ch * 16, Vg + r * EMB + ch * 8);
    }
    cpa_commit();

    const int lr = (lane & 7) + ((lane >> 3) & 1) * 8;
    const int lc = (lane >> 4) * 8;
    const uint32_t aQ = sb + SM_Q + (m0 + lr) * QROW + lc * 2;

    const int krow = (lane & 7) + ((lane >> 4) & 1) * 8;
    const int kcol = ((lane >> 3) & 1) * 8;
    const uint32_t kfrag = krow * QROW + kcol * 2;
    const int vrow = (lane & 7) + ((lane >> 3) & 1) * 8;
    const int vcol = ((lane >> 4) & 1) * 8;
    const uint32_t vfrag = 17408 + vrow * QROW + vcol * 2;

    float Oa[16][4];
#pragma unroll
    for (int t = 0; t < 16; t++)
#pragma unroll
        for (int j = 0; j < 4; j++) Oa[t][j] = 0.f;
    float lacc[4] = {0.f, 0.f, 0.f, 0.f};
    const uint32_t ones2 = 0x3C003C00u;
    const uint32_t onesB[2] = { ones2, ones2 };

    for (int kt = 0; kt < 32; kt++) {
        cpa_wait0();
        __syncthreads();

        if (kt < 31) {
            uint32_t nb = sb + SM_KV + (uint32_t)((kt + 1) & 1) * 34816;
#pragma unroll
            for (int i = 0; i < 4; i++) {
                int idx = tid + i * 256;
                int r = idx >> 4, ch = idx & 15;
                cpa16(nb + r * QROW + ch * 16,
                      Kg + (size_t)((kt + 1) * 64 + r) * EMB + ch * 8);
                cpa16(nb + 17408 + r * QROW + ch * 16,
                      Vg + (size_t)((kt + 1) * 64 + r) * EMB + ch * 8);
            }
            cpa_commit();
        }

        const uint32_t cb = sb + SM_KV + (uint32_t)(kt & 1) * 34816;
        const uint32_t bK = cb + kfrag;
        const uint32_t bV = cb + vfrag;

        // ---- hoist Q fragments for this tile (loop-invariant across blocks)
        uint32_t qf[32];
#pragma unroll
        for (int ks = 0; ks < 8; ks++)
            ldsm4(qf + 4 * ks, aQ + ks * 32);

        // ---- four independent 16-key blocks: S -> exp2 -> PV each ----
#pragma unroll
        for (int nt = 0; nt < 4; nt++) {
            float sacc[8];
#pragma unroll
            for (int j = 0; j < 8; j++) sacc[j] = 0.f;

#pragma unroll
            for (int ks = 0; ks < 8; ks++) {
                uint32_t kh[4];
                ldsm4(kh, bK + nt * 16 * QROW + ks * 32);
                mma16816(sacc,     qf + 4 * ks, kh);
                mma16816(sacc + 4, qf + 4 * ks, kh + 2);
            }

            uint32_t pa[4];
            pa[0] = exp2_h2(sacc[0], sacc[1]);
            pa[1] = exp2_h2(sacc[2], sacc[3]);
            pa[2] = exp2_h2(sacc[4], sacc[5]);
            pa[3] = exp2_h2(sacc[6], sacc[7]);
            mma16816(lacc, pa, onesB);

#pragma unroll
            for (int nc = 0; nc < 8; nc++) {
                uint32_t vh[4];
                ldsm4t(vh, bV + nt * 16 * QROW + nc * 32);
                mma16816(Oa[2 * nc],     pa, vh);
                mma16816(Oa[2 * nc + 1], pa, vh + 2);
            }
        }
    }

    const float inv0 = 1.f / lacc[0];
    const float inv1 = 1.f / lacc[2];

    __syncthreads();
    float* Ob = (float*)sm;
    const int r0 = m0 + (lane >> 2);
#pragma unroll
    for (int t = 0; t < 16; t++) {
        *(float2*)(Ob + (size_t)r0 * 132 + t * 8 + (lane & 3) * 2) =
            make_float2(Oa[t][0] * inv0, Oa[t][1] * inv0);
        *(float2*)(Ob + (size_t)(r0 + 8) * 132 + t * 8 + (lane & 3) * 2) =
            make_float2(Oa[t][2] * inv1, Oa[t][3] * inv1);
    }
    __syncthreads();

    // write A as single fp16 to [b,t,h,e]
    const int bb = bh >> 3, hh = bh & 7;
    const size_t abase = ((size_t)(bb * SEQ + q0) * HEADS + hh) * EMB;
#pragma unroll 4
    for (int i = 0; i < 16; i++) {
        int idx = tid + i * 256;
        int r = idx >> 5, c4 = idx & 31;
        float4 v = *(float4*)(Ob + (size_t)r * 132 + c4 * 4);
        *(uint2*)&g_Ah[abase + (size_t)r * HE + c4 * 4] =
            make_uint2(pk_h2(__float2half_rn(v.x), __float2half_rn(v.y)),
                       pk_h2(__float2half_rn(v.z), __float2half_rn(v.w)));
    }
}

// ---------------------------------------------------------------------------
// Kernel 3: output projection (unchanged from R16).
// ---------------------------------------------------------------------------
#define PJ_A0 0
#define PJ_A1 17408
#define PJ_W0 34816
#define PJ_W1 69632
#define PROJ_SMEM 104448

__global__ __launch_bounds__(256, 2) void proj_tc_kernel(
    float* __restrict__ out,
    const float* __restrict__ bo)
{
    extern __shared__ char sm[];
    const uint32_t sb = smem_u32(sm);

    const int tid  = threadIdx.x;
    const int wid  = tid >> 5;
    const int lane = tid & 31;
    const int mw   = wid & 3;
    const int nw   = wid >> 2;
    const int mc   = blockIdx.x * 64;

#pragma unroll
    for (int i = 0; i < 4; i++) {
        int idx = tid + i * 256;
        int r = idx >> 4, ch = idx & 15;
        cpa16(sb + PJ_A0 + r * XROW + ch * 16,
              g_Ah + (size_t)(mc + r) * HE + ch * 8);
    }
#pragma unroll
    for (int i = 0; i < 8; i++) {
        int idx = tid + i * 256;
        int r = idx >> 4, ch = idx & 15;
        cpa16(sb + PJ_W0 + r * XROW + ch * 16, g_Woh + (size_t)r * EMB + ch * 8);
    }
    cpa_commit();

    const int lr = (lane & 7) + ((lane >> 3) & 1) * 8;
    const int lc = (lane >> 4) * 8;
    const uint32_t afrag = (mw * 16 + lr) * XROW + lc * 2;
    const int vrow = (lane & 7) + ((lane >> 3) & 1) * 8;
    const int vcol = ((lane >> 4) & 1) * 8;
    const uint32_t wfrag = vrow * XROW + (nw * 64 + vcol) * 2;

    float Oa[8][4];
#pragma unroll
    for (int t = 0; t < 8; t++)
#pragma unroll
        for (int j = 0; j < 4; j++) Oa[t][j] = 0.f;

    for (int kb = 0; kb < 8; kb++) {
        cpa_wait0();
        __syncthreads();

        if (kb < 7) {
            uint32_t na = sb + ((kb + 1) & 1 ? PJ_A1 : PJ_A0);
            uint32_t nw2 = sb + ((kb + 1) & 1 ? PJ_W1 : PJ_W0);
#pragma unroll
            for (int i = 0; i < 4; i++) {
                int idx = tid + i * 256;
                int r = idx >> 4, ch = idx & 15;
                cpa16(na + r * XROW + ch * 16,
                      g_Ah + (size_t)(mc + r) * HE + (kb + 1) * 128 + ch * 8);
            }
#pragma unroll
            for (int i = 0; i < 8; i++) {
                int idx = tid + i * 256;
                int r = idx >> 4, ch = idx & 15;
                cpa16(nw2 + r * XROW + ch * 16,
                      g_Woh + (size_t)(kb + 1) * 128 * EMB + (size_t)r * EMB + ch * 8);
            }
            cpa_commit();
        }

        const uint32_t aA = sb + ((kb & 1) ? PJ_A1 : PJ_A0) + afrag;
        const uint32_t bW = sb + ((kb & 1) ? PJ_W1 : PJ_W0) + wfrag;

#pragma unroll
        for (int ks = 0; ks < 8; ks++) {
            uint32_t ah[4];
            ldsm4(ah, aA + ks * 32);
#pragma unroll
            for (int nt = 0; nt < 4; nt++) {
                uint32_t wh[4];
                ldsm4t(wh, bW + ks * 16 * XROW + nt * 32);
                mma16816(Oa[2 * nt],     ah, wh);
                mma16816(Oa[2 * nt + 1], ah, wh + 2);
            }
        }
    }

    const int r0 = mw * 16 + (lane >> 2);
    const int m  = mc + r0;
#pragma unroll
    for (int tt = 0; tt < 8; tt++) {
        int e = nw * 64 + (tt >> 1) * 16 + (tt & 1) * 8 + (lane & 3) * 2;
        float2 bv = *(const float2*)&bo[e];
        *(float2*)&out[(size_t)m * EMB + e] =
            make_float2(Oa[tt][0] + bv.x, Oa[tt][1] + bv.y);
        *(float2*)&out[(size_t)(m + 8) * EMB + e] =
            make_float2(Oa[tt][2] + bv.x, Oa[tt][3] + bv.y);
    }
}

// ---------------------------------------------------------------------------
extern "C" void kernel_launch(void* const* d_in, const int* in_sizes, int n_in,
                              void* d_out, int out_size)
{
    const float* x  = (const float*)d_in[0];
    const float* Wq = (const float*)d_in[1];
    const float* Wk = (const float*)d_in[2];
    const float* Wv = (const float*)d_in[3];
    const float* Wo = (const float*)d_in[4];
    const float* bo = (const float*)d_in[5];
    float* out = (float*)d_out;

    cudaFuncSetAttribute(qkv_tc_kernel,
                         cudaFuncAttributeMaxDynamicSharedMemorySize, QKV_SMEM);
    cudaFuncSetAttribute(attn_mma_kernel,
                         cudaFuncAttributeMaxDynamicSharedMemorySize, ATTN_SMEM);
    cudaFuncSetAttribute(proj_tc_kernel,
                         cudaFuncAttributeMaxDynamicSharedMemorySize, PROJ_SMEM);

    prep_kernel<<<dim3(1024, 5), 256>>>(x, Wq, Wk, Wv, Wo);
    qkv_tc_kernel<<<dim3(BT / 64, 3), 256, QKV_SMEM>>>();
    attn_mma_kernel<<<dim3(SEQ / 128, NB * HEADS), 256, ATTN_SMEM>>>();
    proj_tc_kernel<<<dim3(BT / 64), 256, PROJ_SMEM>>>(out, bo);
}